// round 2
// baseline (speedup 1.0000x reference)
#include <cuda_runtime.h>

// focal_loss: out = COEF * sum_i ( idx==0 ? log(p) : idx==1 ? log(1-p) : 0 )
// COEF = 0.1 * (1-0.8)^2 = 0.004
// Single fused kernel: grid-stride streaming reduction (128 MiB, HBM-bound)
// + threadfence last-block-done final fold. Deterministic (fixed-order float
// sums; atomics only on an int counter). No allocations; scratch in
// __device__ globals. Counter self-resets -> graph-replay safe.

#define NBLOCKS  2048
#define NTHREADS 256

__device__ float        g_partials[NBLOCKS];
__device__ unsigned int g_count = 0;

__device__ __forceinline__ float term_of(float p, int idx) {
    // idx==0 -> log(p); idx==1 -> log(1-p); else log(1)=0. One MUFU per elem.
    float x = (idx == 0) ? p : ((idx == 1) ? (1.0f - p) : 1.0f);
    return __logf(x);
}

__device__ __forceinline__ float block_reduce(float acc) {
    #pragma unroll
    for (int o = 16; o > 0; o >>= 1)
        acc += __shfl_down_sync(0xffffffffu, acc, o);
    __shared__ float s[NTHREADS / 32];
    if ((threadIdx.x & 31) == 0) s[threadIdx.x >> 5] = acc;
    __syncthreads();
    float v = 0.0f;
    if (threadIdx.x < 32) {
        v = (threadIdx.x < NTHREADS / 32) ? s[threadIdx.x] : 0.0f;
        #pragma unroll
        for (int o = 4; o > 0; o >>= 1)
            v += __shfl_down_sync(0xffffffffu, v, o);
    }
    return v;   // valid in thread 0
}

__global__ void __launch_bounds__(NTHREADS)
focal_loss_fused(const float* __restrict__ p, const int* __restrict__ idx,
                 int n, int n4, float* __restrict__ out) {
    const float4* __restrict__ p4 = reinterpret_cast<const float4*>(p);
    const int4*   __restrict__ i4 = reinterpret_cast<const int4*>(idx);

    const int stride = NBLOCKS * NTHREADS;
    int i = blockIdx.x * NTHREADS + threadIdx.x;

    float acc = 0.0f;

    // Batched grid-stride: front-load 8 x 128-bit loads per outer iteration
    // (MLP_p1 ~ 8) before the MUFU chain.
    for (; i + 3 * stride < n4; i += 4 * stride) {
        float4 a0 = p4[i];
        float4 a1 = p4[i + stride];
        float4 a2 = p4[i + 2 * stride];
        float4 a3 = p4[i + 3 * stride];
        int4   b0 = i4[i];
        int4   b1 = i4[i + stride];
        int4   b2 = i4[i + 2 * stride];
        int4   b3 = i4[i + 3 * stride];
        acc += term_of(a0.x, b0.x) + term_of(a0.y, b0.y)
             + term_of(a0.z, b0.z) + term_of(a0.w, b0.w);
        acc += term_of(a1.x, b1.x) + term_of(a1.y, b1.y)
             + term_of(a1.z, b1.z) + term_of(a1.w, b1.w);
        acc += term_of(a2.x, b2.x) + term_of(a2.y, b2.y)
             + term_of(a2.z, b2.z) + term_of(a2.w, b2.w);
        acc += term_of(a3.x, b3.x) + term_of(a3.y, b3.y)
             + term_of(a3.z, b3.z) + term_of(a3.w, b3.w);
    }
    for (; i < n4; i += stride) {
        float4 a = p4[i];
        int4   b = i4[i];
        acc += term_of(a.x, b.x) + term_of(a.y, b.y)
             + term_of(a.z, b.z) + term_of(a.w, b.w);
    }

    float bsum = block_reduce(acc);
    __shared__ bool s_last;
    if (threadIdx.x == 0) {
        g_partials[blockIdx.x] = bsum;
        __threadfence();
        unsigned int done = atomicAdd(&g_count, 1u);
        s_last = (done == (unsigned int)(gridDim.x - 1));
    }
    __syncthreads();

    if (s_last) {
        // Last block: fold all partials (visible via threadfence+atomic chain)
        float f = 0.0f;
        for (int k = threadIdx.x; k < NBLOCKS; k += NTHREADS)
            f += g_partials[k];
        // scalar tail (n not multiple of 4) — empty for N=16M, kept for safety
        for (int k = n4 * 4 + (int)threadIdx.x; k < n; k += NTHREADS)
            f += term_of(p[k], idx[k]);

        __syncthreads();   // reuse of shared s[] inside block_reduce
        float total = block_reduce(f);
        if (threadIdx.x == 0) {
            out[0] = 0.004f * total;   // COEF
            g_count = 0;               // reset for next graph replay
        }
    }
}

extern "C" void kernel_launch(void* const* d_in, const int* in_sizes, int n_in,
                              void* d_out, int out_size) {
    const float* p   = (const float*)d_in[0];
    const int*   idx = (const int*)d_in[1];
    float* out = (float*)d_out;
    int n  = in_sizes[0];
    int n4 = n >> 2;

    focal_loss_fused<<<NBLOCKS, NTHREADS>>>(p, idx, n, n4, out);
}